// round 13
// baseline (speedup 1.0000x reference)
#include <cuda_runtime.h>
#include <cuda_fp16.h>
#include <cstdint>

// ---------------------------------------------------------------------------
// GNNTransductiveEdgeHead, R13:
//  - MLP: persistent CTA, two 8-warp streams, 128-row tiles, fp16 GEMM
//    (fp32 accum), DOUBLE-BUFFERED A per stream (staging off critical path,
//    3 barriers/iter instead of 4). W converted fp32->fp16 in-kernel.
//  - edge dot: 16 lanes/edge, 4 edges/warp, half2-math dot.
// ---------------------------------------------------------------------------

#define DD 128
#define TILE 128           // rows per stream-tile
#define MAX_NODES 100000
#define NSM 148

// SMEM layout (bytes): rows are 128 fp16 = 256B, XOR-swizzled 16B chunks.
#define P_W1H 0
#define P_W2H 32768
#define A_BASE 65536       // stream g: A_BASE + g*65536 + buf*32768
#define B1_OFF 196608
#define B2_OFF 197120
#define SMEM_TOTAL 197632

__device__ uint4 g_h2h[MAX_NODES * 16];          // h2 as fp16, 256B per node

__device__ __forceinline__ uint32_t smem_u32(const void* p) {
    uint32_t a;
    asm("{ .reg .u64 t; cvta.to.shared.u64 t, %1; cvt.u32.u64 %0, t; }"
        : "=r"(a) : "l"(p));
    return a;
}
__device__ __forceinline__ void ldmatrix_x4(uint32_t& r0, uint32_t& r1,
                                            uint32_t& r2, uint32_t& r3,
                                            uint32_t addr) {
    asm volatile("ldmatrix.sync.aligned.m8n8.x4.shared.b16 {%0,%1,%2,%3}, [%4];"
                 : "=r"(r0), "=r"(r1), "=r"(r2), "=r"(r3) : "r"(addr));
}
__device__ __forceinline__ void ldmatrix_x4_trans(uint32_t& r0, uint32_t& r1,
                                                  uint32_t& r2, uint32_t& r3,
                                                  uint32_t addr) {
    asm volatile("ldmatrix.sync.aligned.m8n8.x4.trans.shared.b16 {%0,%1,%2,%3}, [%4];"
                 : "=r"(r0), "=r"(r1), "=r"(r2), "=r"(r3) : "r"(addr));
}
__device__ __forceinline__ void mma_f16(float* c, const uint32_t* a,
                                        uint32_t b0, uint32_t b1) {
    asm volatile(
        "mma.sync.aligned.m16n8k16.row.col.f32.f16.f16.f32 "
        "{%0,%1,%2,%3}, {%4,%5,%6,%7}, {%8,%9}, {%0,%1,%2,%3};"
        : "+f"(c[0]), "+f"(c[1]), "+f"(c[2]), "+f"(c[3])
        : "r"(a[0]), "r"(a[1]), "r"(a[2]), "r"(a[3]), "r"(b0), "r"(b1));
}
__device__ __forceinline__ uint32_t packh2(float x, float y) {
    __half2 h = __floats2half2_rn(x, y);
    return *(uint32_t*)&h;
}
#define GBAR(gid) asm volatile("bar.sync %0, %1;" :: "r"((gid) + 1), "r"(256) : "memory")

// fp16 MMA over one staged A tile vs one W panel: 8 ks x (6 LDSM + 16 HMMA).
__device__ __forceinline__ void mma_layer(float acc[4][4][4],
                                          uint32_t aB, uint32_t pB,
                                          int hA, int x7, int ng) {
#pragma unroll
    for (int ks = 0; ks < 8; ks++) {
        uint32_t ah[4][4];
#pragma unroll
        for (int mt = 0; mt < 4; mt++) {
            const uint32_t off = mt * 4096 + ((((2 * ks + hA) ^ x7)) << 4);
            ldmatrix_x4(ah[mt][0], ah[mt][1], ah[mt][2], ah[mt][3], aB + off);
        }
        uint32_t bh[4][2];
#pragma unroll
        for (int hf = 0; hf < 2; hf++) {
            const uint32_t off = ks * 4096 +
                ((((4 * ng + 2 * hf + hA) ^ x7)) << 4);
            uint32_t r0, r1, r2, r3;
            ldmatrix_x4_trans(r0, r1, r2, r3, pB + off);
            bh[2 * hf][0] = r0; bh[2 * hf][1] = r1;
            bh[2 * hf + 1][0] = r2; bh[2 * hf + 1][1] = r3;
        }
#pragma unroll
        for (int mt = 0; mt < 4; mt++)
#pragma unroll
            for (int nt = 0; nt < 4; nt++)
                mma_f16(acc[mt][nt], ah[mt], bh[nt][0], bh[nt][1]);
    }
}

// Stage one 128-row X tile (fp32 global -> fp16 swizzled smem buffer).
__device__ __forceinline__ void stage_tile(char* smem, uint32_t abuf,
                                           const float* __restrict__ X,
                                           int t, int N, int tg) {
    const int row = tg >> 1, hf = tg & 1;
    const int grow = t * TILE + row;
    const bool ok = grow < N;
    const float4* src = (const float4*)(X + (long long)grow * DD + hf * 64);
    char* d = smem + abuf + row * 256;
    const int r7 = row & 7;
#pragma unroll
    for (int q = 0; q < 8; q++) {
        float4 a = ok ? src[2 * q]     : make_float4(0, 0, 0, 0);
        float4 b = ok ? src[2 * q + 1] : make_float4(0, 0, 0, 0);
        uint4 v;
        v.x = packh2(a.x, a.y);
        v.y = packh2(a.z, a.w);
        v.z = packh2(b.x, b.y);
        v.w = packh2(b.z, b.w);
        *(uint4*)(d + (((8 * hf + q) ^ r7) << 4)) = v;
    }
}

// ---------------------------------------------------------------------------
// Persistent fused MLP: 512 thr = 2 streams x 8 warps; stream tile 128 rows;
// warp (mg=w&1, ng=w>>1) owns rows [64mg,64mg+64) x cols [32ng,32ng+32).
// Double-buffered A: stage next tile into alt buffer mid-iteration.
// ---------------------------------------------------------------------------
__global__ void __launch_bounds__(512, 1) mlp_fused_kernel(
    const float* __restrict__ X,
    const float* __restrict__ W1, const float* __restrict__ W2,
    const float* __restrict__ bias1, const float* __restrict__ bias2,
    uint4* __restrict__ H2h,
    int N, int T)
{
    extern __shared__ __align__(16) char smem[];
    const uint32_t sb = smem_u32(smem);
    const int tid  = threadIdx.x;
    const int g    = tid >> 8;        // stream 0/1
    const int tg   = tid & 255;
    const int warp = tg >> 5;
    const int lane = tid & 31;
    const int mg = warp & 1;
    const int ng = warp >> 1;

    // --- Prologue: load W fp32, convert to fp16, store swizzled ---
    {
        const float* wsrc[2] = {W1, W2};
        const uint32_t pdst[2] = {P_W1H, P_W2H};
#pragma unroll
        for (int i = 0; i < 8; i++) {
            int idx = tid + i * 512;          // 4096 chunks (16B fp16 each)
            int panel = idx >> 11;
            int rem   = idx & 2047;
            int row   = rem >> 4;
            int c     = rem & 15;             // chunk = 8 cols
            const float4* s = (const float4*)(wsrc[panel] + row * DD + c * 8);
            const float4 a = s[0], b = s[1];
            uint4 v;
            v.x = packh2(a.x, a.y);
            v.y = packh2(a.z, a.w);
            v.z = packh2(b.x, b.y);
            v.w = packh2(b.z, b.w);
            *(uint4*)(smem + pdst[panel] + row * 256 +
                      ((c ^ (row & 7)) << 4)) = v;
        }
    }
    if (tid < DD) {
        ((float*)(smem + B1_OFF))[tid] = bias1[tid];
        ((float*)(smem + B2_OFF))[tid] = bias2[tid];
    }

    const uint32_t ABg = A_BASE + g * 65536;

    // Stage first tile into buffer 0.
    int t = 2 * blockIdx.x + g;
    if (t < T) stage_tile(smem, ABg, X, t, N, tg);
    __syncthreads();   // W panels + first tiles visible

    const int hA = lane >> 4;
    const int x7 = lane & 7;
    const uint32_t aRow = (uint32_t)(mg * 64 + (lane & 15));
    const uint32_t bRow = (uint32_t)(lane & 15) * 256;
    const uint32_t p1 = sb + P_W1H + bRow;
    const uint32_t p2 = sb + P_W2H + bRow;
    const float* sB1 = (const float*)(smem + B1_OFF);
    const float* sB2 = (const float*)(smem + B2_OFF);

    int p = 0;   // current A buffer parity
    for (; t < T; t += 2 * NSM) {
        const int tn = t + 2 * NSM;
        const bool have_next = tn < T;
        const uint32_t ACUR = ABg + (uint32_t)p * 32768;
        const uint32_t AALT = ABg + (uint32_t)(p ^ 1) * 32768;
        const uint32_t aB = sb + ACUR + aRow * 256;

        float acc[4][4][4];
#pragma unroll
        for (int mt = 0; mt < 4; mt++)
#pragma unroll
            for (int nt = 0; nt < 4; nt++)
#pragma unroll
                for (int c = 0; c < 4; c++) acc[mt][nt][c] = 0.f;

        // ---- Layer 1 MMAs (read A-cur = x) ----
        mma_layer(acc, aB, p1, hA, x7, ng);
        GBAR(g);   // A-cur free for h1 writes

        // ---- Epilogue 1: h1 = relu(acc+b1) -> fp16 A-cur ----
#pragma unroll
        for (int mt = 0; mt < 4; mt++) {
            const int r0 = mg * 64 + mt * 16 + (lane >> 2);
            const int r1 = r0 + 8;
#pragma unroll
            for (int nt = 0; nt < 4; nt++) {
                const int cc = ng * 32 + nt * 8 + (lane & 3) * 2;
                const float bx = sB1[cc], by = sB1[cc + 1];
                const uint32_t w0 = ((4 * ng + nt) ^ (r0 & 7)) * 16 + 4 * (lane & 3);
                const uint32_t w1 = ((4 * ng + nt) ^ (r1 & 7)) * 16 + 4 * (lane & 3);
                *(uint32_t*)(smem + ACUR + r0 * 256 + w0) =
                    packh2(fmaxf(acc[mt][nt][0] + bx, 0.f),
                           fmaxf(acc[mt][nt][1] + by, 0.f));
                *(uint32_t*)(smem + ACUR + r1 * 256 + w1) =
                    packh2(fmaxf(acc[mt][nt][2] + bx, 0.f),
                           fmaxf(acc[mt][nt][3] + by, 0.f));
            }
        }

        // ---- Stage next tile into A-alt (independent of h1 sync) ----
        if (have_next) stage_tile(smem, AALT, X, tn, N, tg);
        GBAR(g);   // h1 visible (and stage issued)

        // ---- Layer 2 MMAs (read A-cur = h1) ----
#pragma unroll
        for (int mt = 0; mt < 4; mt++)
#pragma unroll
            for (int nt = 0; nt < 4; nt++)
#pragma unroll
                for (int c = 0; c < 4; c++) acc[mt][nt][c] = 0.f;
        mma_layer(acc, aB, p2, hA, x7, ng);
        GBAR(g);   // A-cur read done (next iter stages over it);
                   // A-alt staging complete (next iter reads it)

        // ---- Epilogue 2: h2 = relu(acc+b2) -> global fp16 ----
        {
            __half* H = (__half*)H2h;
            const int rowb = t * TILE + mg * 64;
#pragma unroll
            for (int mt = 0; mt < 4; mt++) {
                const int r0 = rowb + mt * 16 + (lane >> 2);
                const int r1 = r0 + 8;
                const bool ok0 = r0 < N, ok1 = r1 < N;
#pragma unroll
                for (int nt = 0; nt < 4; nt++) {
                    const int cc = ng * 32 + nt * 8 + (lane & 3) * 2;
                    const float bx = sB2[cc], by = sB2[cc + 1];
                    if (ok0) {
                        __half2 v = __floats2half2_rn(
                            fmaxf(acc[mt][nt][0] + bx, 0.f),
                            fmaxf(acc[mt][nt][1] + by, 0.f));
                        *(__half2*)(H + (long long)r0 * DD + cc) = v;
                    }
                    if (ok1) {
                        __half2 v = __floats2half2_rn(
                            fmaxf(acc[mt][nt][2] + bx, 0.f),
                            fmaxf(acc[mt][nt][3] + by, 0.f));
                        *(__half2*)(H + (long long)r1 * DD + cc) = v;
                    }
                }
            }
        }
        p ^= 1;
    }
}

// ---------------------------------------------------------------------------
// Edge decode: 16 lanes/edge, 4 edges/warp, half2-math dot.
// ---------------------------------------------------------------------------
__device__ __forceinline__ float dot16B(uint4 a, uint4 b) {
    __half2 p0 = __hmul2(*(const __half2*)&a.x, *(const __half2*)&b.x);
    p0 = __hfma2(*(const __half2*)&a.z, *(const __half2*)&b.z, p0);
    __half2 p1 = __hmul2(*(const __half2*)&a.y, *(const __half2*)&b.y);
    p1 = __hfma2(*(const __half2*)&a.w, *(const __half2*)&b.w, p1);
    const float2 f0 = __half22float2(p0);
    const float2 f1 = __half22float2(p1);
    return (f0.x + f0.y) + (f1.x + f1.y);
}

__global__ void __launch_bounds__(256) edge_dot_kernel(
    const uint4* __restrict__ H16,
    const int* __restrict__ edge_index,
    const int* __restrict__ lbl,
    float* __restrict__ out,
    float* __restrict__ lblout,
    int E, int N)
{
    const int gwarp = (blockIdx.x * blockDim.x + threadIdx.x) >> 5;
    const int lane  = threadIdx.x & 31;
    const int el = lane & 15;
    const int eh = lane >> 4;
    const int base = gwarp * 4;
    if (base >= E) return;

    const int eA = base + eh;
    const int eB = base + eh + 2;
    const bool okA = eA < E, okB = eB < E;
    const int iA = okA ? eA : 0;
    const int iB = okB ? eB : 0;

    int sA = edge_index[iA], dA = edge_index[E + iA];
    int sB = edge_index[iB], dB = edge_index[E + iB];
    sA = min(max(sA, 0), N - 1); dA = min(max(dA, 0), N - 1);
    sB = min(max(sB, 0), N - 1); dB = min(max(dB, 0), N - 1);

    const uint4 vsA = H16[sA * 16 + el];
    const uint4 vdA = H16[dA * 16 + el];
    const uint4 vsB = H16[sB * 16 + el];
    const uint4 vdB = H16[dB * 16 + el];

    float rA = dot16B(vsA, vdA);
    float rB = dot16B(vsB, vdB);

#pragma unroll
    for (int o = 8; o > 0; o >>= 1) {
        rA += __shfl_xor_sync(0xFFFFFFFFu, rA, o);
        rB += __shfl_xor_sync(0xFFFFFFFFu, rB, o);
    }

    if (el == 0) {
        if (okA) out[eA] = rA;
        if (okB) out[eB] = rB;
    }
    if (lblout && el == 1) {
        if (okA) lblout[eA] = (float)lbl[eA];
        if (okB) lblout[eB] = (float)lbl[eB];
    }
}

extern "C" void kernel_launch(void* const* d_in, const int* in_sizes, int n_in,
                              void* d_out, int out_size)
{
    const float* x   = (const float*)d_in[0];
    const int*   ei  = (const int*)d_in[1];
    const int*   lbl = (const int*)d_in[2];
    const float* W1  = (const float*)d_in[3];
    const float* b1  = (const float*)d_in[4];
    const float* W2  = (const float*)d_in[5];
    const float* b2  = (const float*)d_in[6];

    int N = in_sizes[0] / DD;   // 100000
    int E = in_sizes[2];        // 500000

    uint4* h2h;
    cudaGetSymbolAddress((void**)&h2h, g_h2h);

    cudaFuncSetAttribute(mlp_fused_kernel,
                         cudaFuncAttributeMaxDynamicSharedMemorySize, SMEM_TOTAL);

    int T = (N + TILE - 1) / TILE;
    mlp_fused_kernel<<<NSM, 512, SMEM_TOTAL>>>(x, W1, W2, b1, b2, h2h, N, T);

    float* out = (float*)d_out;
    float* lblout = (out_size >= 2 * E) ? out + E : nullptr;
    int warps  = (E + 3) / 4;            // 4 edges per warp
    int blocks = (warps + 7) / 8;        // 8 warps per block
    edge_dot_kernel<<<blocks, 256>>>(h2h, ei, lbl, out, lblout, E, N);
}

// round 14
// speedup vs baseline: 1.0048x; 1.0048x over previous
#include <cuda_runtime.h>
#include <cuda_fp16.h>
#include <cstdint>

// ---------------------------------------------------------------------------
// GNNTransductiveEdgeHead, R14:
//  - MLP: persistent CTA, two 8-warp streams, 128-row tiles, fp16 GEMM
//    (fp32 accum). Separate x / h1 SMEM buffers -> 2 barriers/iter, and the
//    global-store epilogue overlaps the next tile's layer-1 MMAs.
//  - edge dot: 16 lanes/edge, 4 edges/warp, half2-math dot (unchanged).
// ---------------------------------------------------------------------------

#define DD 128
#define TILE 128           // rows per stream-tile
#define MAX_NODES 100000
#define NSM 148

// SMEM layout (bytes): rows are 128 fp16 = 256B, XOR-swizzled 16B chunks.
#define P_W1H 0
#define P_W2H 32768
#define A_BASE 65536       // stream g: XBUF = A_BASE + g*65536, H1BUF = +32768
#define B1_OFF 196608
#define B2_OFF 197120
#define SMEM_TOTAL 197632

__device__ uint4 g_h2h[MAX_NODES * 16];          // h2 as fp16, 256B per node

__device__ __forceinline__ uint32_t smem_u32(const void* p) {
    uint32_t a;
    asm("{ .reg .u64 t; cvta.to.shared.u64 t, %1; cvt.u32.u64 %0, t; }"
        : "=r"(a) : "l"(p));
    return a;
}
__device__ __forceinline__ void ldmatrix_x4(uint32_t& r0, uint32_t& r1,
                                            uint32_t& r2, uint32_t& r3,
                                            uint32_t addr) {
    asm volatile("ldmatrix.sync.aligned.m8n8.x4.shared.b16 {%0,%1,%2,%3}, [%4];"
                 : "=r"(r0), "=r"(r1), "=r"(r2), "=r"(r3) : "r"(addr));
}
__device__ __forceinline__ void ldmatrix_x4_trans(uint32_t& r0, uint32_t& r1,
                                                  uint32_t& r2, uint32_t& r3,
                                                  uint32_t addr) {
    asm volatile("ldmatrix.sync.aligned.m8n8.x4.trans.shared.b16 {%0,%1,%2,%3}, [%4];"
                 : "=r"(r0), "=r"(r1), "=r"(r2), "=r"(r3) : "r"(addr));
}
__device__ __forceinline__ void mma_f16(float* c, const uint32_t* a,
                                        uint32_t b0, uint32_t b1) {
    asm volatile(
        "mma.sync.aligned.m16n8k16.row.col.f32.f16.f16.f32 "
        "{%0,%1,%2,%3}, {%4,%5,%6,%7}, {%8,%9}, {%0,%1,%2,%3};"
        : "+f"(c[0]), "+f"(c[1]), "+f"(c[2]), "+f"(c[3])
        : "r"(a[0]), "r"(a[1]), "r"(a[2]), "r"(a[3]), "r"(b0), "r"(b1));
}
__device__ __forceinline__ uint32_t packh2(float x, float y) {
    __half2 h = __floats2half2_rn(x, y);
    return *(uint32_t*)&h;
}
#define GBAR(gid) asm volatile("bar.sync %0, %1;" :: "r"((gid) + 1), "r"(256) : "memory")

// fp16 MMA over one staged A tile vs one W panel: 8 ks x (6 LDSM + 16 HMMA).
__device__ __forceinline__ void mma_layer(float acc[4][4][4],
                                          uint32_t aB, uint32_t pB,
                                          int hA, int x7, int ng) {
#pragma unroll
    for (int ks = 0; ks < 8; ks++) {
        uint32_t ah[4][4];
#pragma unroll
        for (int mt = 0; mt < 4; mt++) {
            const uint32_t off = mt * 4096 + ((((2 * ks + hA) ^ x7)) << 4);
            ldmatrix_x4(ah[mt][0], ah[mt][1], ah[mt][2], ah[mt][3], aB + off);
        }
        uint32_t bh[4][2];
#pragma unroll
        for (int hf = 0; hf < 2; hf++) {
            const uint32_t off = ks * 4096 +
                ((((4 * ng + 2 * hf + hA) ^ x7)) << 4);
            uint32_t r0, r1, r2, r3;
            ldmatrix_x4_trans(r0, r1, r2, r3, pB + off);
            bh[2 * hf][0] = r0; bh[2 * hf][1] = r1;
            bh[2 * hf + 1][0] = r2; bh[2 * hf + 1][1] = r3;
        }
#pragma unroll
        for (int mt = 0; mt < 4; mt++)
#pragma unroll
            for (int nt = 0; nt < 4; nt++)
                mma_f16(acc[mt][nt], ah[mt], bh[nt][0], bh[nt][1]);
    }
}

// Stage one 128-row X tile (fp32 global -> fp16 swizzled smem buffer).
__device__ __forceinline__ void stage_tile(char* smem, uint32_t abuf,
                                           const float* __restrict__ X,
                                           int t, int N, int tg) {
    const int row = tg >> 1, hf = tg & 1;
    const int grow = t * TILE + row;
    const bool ok = grow < N;
    const float4* src = (const float4*)(X + (long long)grow * DD + hf * 64);
    char* d = smem + abuf + row * 256;
    const int r7 = row & 7;
#pragma unroll
    for (int q = 0; q < 8; q++) {
        float4 a = ok ? src[2 * q]     : make_float4(0, 0, 0, 0);
        float4 b = ok ? src[2 * q + 1] : make_float4(0, 0, 0, 0);
        uint4 v;
        v.x = packh2(a.x, a.y);
        v.y = packh2(a.z, a.w);
        v.z = packh2(b.x, b.y);
        v.w = packh2(b.z, b.w);
        *(uint4*)(d + (((8 * hf + q) ^ r7) << 4)) = v;
    }
}

// ---------------------------------------------------------------------------
// Persistent fused MLP: 512 thr = 2 streams x 8 warps; stream tile 128 rows;
// warp (mg=w&1, ng=w>>1) owns rows [64mg,64mg+64) x cols [32ng,32ng+32).
// Separate XBUF / H1BUF: 2 barriers per iteration; epilogue-2 unfenced.
// ---------------------------------------------------------------------------
__global__ void __launch_bounds__(512, 1) mlp_fused_kernel(
    const float* __restrict__ X,
    const float* __restrict__ W1, const float* __restrict__ W2,
    const float* __restrict__ bias1, const float* __restrict__ bias2,
    uint4* __restrict__ H2h,
    int N, int T)
{
    extern __shared__ __align__(16) char smem[];
    const uint32_t sb = smem_u32(smem);
    const int tid  = threadIdx.x;
    const int g    = tid >> 8;        // stream 0/1
    const int tg   = tid & 255;
    const int warp = tg >> 5;
    const int lane = tid & 31;
    const int mg = warp & 1;
    const int ng = warp >> 1;

    // --- Prologue: load W fp32, convert to fp16, store swizzled ---
    {
        const float* wsrc[2] = {W1, W2};
        const uint32_t pdst[2] = {P_W1H, P_W2H};
#pragma unroll
        for (int i = 0; i < 8; i++) {
            int idx = tid + i * 512;          // 4096 chunks (16B fp16 each)
            int panel = idx >> 11;
            int rem   = idx & 2047;
            int row   = rem >> 4;
            int c     = rem & 15;             // chunk = 8 cols
            const float4* s = (const float4*)(wsrc[panel] + row * DD + c * 8);
            const float4 a = s[0], b = s[1];
            uint4 v;
            v.x = packh2(a.x, a.y);
            v.y = packh2(a.z, a.w);
            v.z = packh2(b.x, b.y);
            v.w = packh2(b.z, b.w);
            *(uint4*)(smem + pdst[panel] + row * 256 +
                      ((c ^ (row & 7)) << 4)) = v;
        }
    }
    if (tid < DD) {
        ((float*)(smem + B1_OFF))[tid] = bias1[tid];
        ((float*)(smem + B2_OFF))[tid] = bias2[tid];
    }

    const uint32_t XBUF  = A_BASE + g * 65536;
    const uint32_t H1BUF = XBUF + 32768;

    // Stage first tile into XBUF.
    int t = 2 * blockIdx.x + g;
    if (t < T) stage_tile(smem, XBUF, X, t, N, tg);
    __syncthreads();   // W panels + first tiles visible

    const int hA = lane >> 4;
    const int x7 = lane & 7;
    const uint32_t aRow = (uint32_t)(mg * 64 + (lane & 15));
    const uint32_t aX  = sb + XBUF  + aRow * 256;
    const uint32_t aH1 = sb + H1BUF + aRow * 256;
    const uint32_t bRow = (uint32_t)(lane & 15) * 256;
    const uint32_t p1 = sb + P_W1H + bRow;
    const uint32_t p2 = sb + P_W2H + bRow;
    const float* sB1 = (const float*)(smem + B1_OFF);
    const float* sB2 = (const float*)(smem + B2_OFF);

    for (; t < T; t += 2 * NSM) {
        const int tn = t + 2 * NSM;
        const bool have_next = tn < T;

        float acc[4][4][4];
#pragma unroll
        for (int mt = 0; mt < 4; mt++)
#pragma unroll
            for (int nt = 0; nt < 4; nt++)
#pragma unroll
                for (int c = 0; c < 4; c++) acc[mt][nt][c] = 0.f;

        // ---- Layer 1 MMAs (read XBUF) ----
        mma_layer(acc, aX, p1, hA, x7, ng);
        GBAR(g);   // all warps: L1 reads done (and, by program order,
                   // prev iter's L2 reads of H1BUF done) -> both writable

        // ---- Epilogue 1: h1 = relu(acc+b1) -> H1BUF ----
#pragma unroll
        for (int mt = 0; mt < 4; mt++) {
            const int r0 = mg * 64 + mt * 16 + (lane >> 2);
            const int r1 = r0 + 8;
#pragma unroll
            for (int nt = 0; nt < 4; nt++) {
                const int cc = ng * 32 + nt * 8 + (lane & 3) * 2;
                const float bx = sB1[cc], by = sB1[cc + 1];
                const uint32_t w0 = ((4 * ng + nt) ^ (r0 & 7)) * 16 + 4 * (lane & 3);
                const uint32_t w1 = ((4 * ng + nt) ^ (r1 & 7)) * 16 + 4 * (lane & 3);
                *(uint32_t*)(smem + H1BUF + r0 * 256 + w0) =
                    packh2(fmaxf(acc[mt][nt][0] + bx, 0.f),
                           fmaxf(acc[mt][nt][1] + by, 0.f));
                *(uint32_t*)(smem + H1BUF + r1 * 256 + w1) =
                    packh2(fmaxf(acc[mt][nt][2] + bx, 0.f),
                           fmaxf(acc[mt][nt][3] + by, 0.f));
            }
        }

        // ---- Stage next tile into XBUF (safe: all L1 reads done) ----
        if (have_next) stage_tile(smem, XBUF, X, tn, N, tg);
        GBAR(g);   // h1 + next x visible

        // ---- Layer 2 MMAs (read H1BUF) ----
#pragma unroll
        for (int mt = 0; mt < 4; mt++)
#pragma unroll
            for (int nt = 0; nt < 4; nt++)
#pragma unroll
                for (int c = 0; c < 4; c++) acc[mt][nt][c] = 0.f;
        mma_layer(acc, aH1, p2, hA, x7, ng);

        // ---- Epilogue 2: h2 = relu(acc+b2) -> global fp16 (no barrier:
        //      overlaps next iteration's layer-1 MMAs) ----
        {
            __half* H = (__half*)H2h;
            const int rowb = t * TILE + mg * 64;
#pragma unroll
            for (int mt = 0; mt < 4; mt++) {
                const int r0 = rowb + mt * 16 + (lane >> 2);
                const int r1 = r0 + 8;
                const bool ok0 = r0 < N, ok1 = r1 < N;
#pragma unroll
                for (int nt = 0; nt < 4; nt++) {
                    const int cc = ng * 32 + nt * 8 + (lane & 3) * 2;
                    const float bx = sB2[cc], by = sB2[cc + 1];
                    if (ok0) {
                        __half2 v = __floats2half2_rn(
                            fmaxf(acc[mt][nt][0] + bx, 0.f),
                            fmaxf(acc[mt][nt][1] + by, 0.f));
                        *(__half2*)(H + (long long)r0 * DD + cc) = v;
                    }
                    if (ok1) {
                        __half2 v = __floats2half2_rn(
                            fmaxf(acc[mt][nt][2] + bx, 0.f),
                            fmaxf(acc[mt][nt][3] + by, 0.f));
                        *(__half2*)(H + (long long)r1 * DD + cc) = v;
                    }
                }
            }
        }
    }
}

// ---------------------------------------------------------------------------
// Edge decode: 16 lanes/edge, 4 edges/warp, half2-math dot.
// ---------------------------------------------------------------------------
__device__ __forceinline__ float dot16B(uint4 a, uint4 b) {
    __half2 p0 = __hmul2(*(const __half2*)&a.x, *(const __half2*)&b.x);
    p0 = __hfma2(*(const __half2*)&a.z, *(const __half2*)&b.z, p0);
    __half2 p1 = __hmul2(*(const __half2*)&a.y, *(const __half2*)&b.y);
    p1 = __hfma2(*(const __half2*)&a.w, *(const __half2*)&b.w, p1);
    const float2 f0 = __half22float2(p0);
    const float2 f1 = __half22float2(p1);
    return (f0.x + f0.y) + (f1.x + f1.y);
}

__global__ void __launch_bounds__(256) edge_dot_kernel(
    const uint4* __restrict__ H16,
    const int* __restrict__ edge_index,
    const int* __restrict__ lbl,
    float* __restrict__ out,
    float* __restrict__ lblout,
    int E, int N)
{
    const int gwarp = (blockIdx.x * blockDim.x + threadIdx.x) >> 5;
    const int lane  = threadIdx.x & 31;
    const int el = lane & 15;
    const int eh = lane >> 4;
    const int base = gwarp * 4;
    if (base >= E) return;

    const int eA = base + eh;
    const int eB = base + eh + 2;
    const bool okA = eA < E, okB = eB < E;
    const int iA = okA ? eA : 0;
    const int iB = okB ? eB : 0;

    int sA = edge_index[iA], dA = edge_index[E + iA];
    int sB = edge_index[iB], dB = edge_index[E + iB];
    sA = min(max(sA, 0), N - 1); dA = min(max(dA, 0), N - 1);
    sB = min(max(sB, 0), N - 1); dB = min(max(dB, 0), N - 1);

    const uint4 vsA = H16[sA * 16 + el];
    const uint4 vdA = H16[dA * 16 + el];
    const uint4 vsB = H16[sB * 16 + el];
    const uint4 vdB = H16[dB * 16 + el];

    float rA = dot16B(vsA, vdA);
    float rB = dot16B(vsB, vdB);

#pragma unroll
    for (int o = 8; o > 0; o >>= 1) {
        rA += __shfl_xor_sync(0xFFFFFFFFu, rA, o);
        rB += __shfl_xor_sync(0xFFFFFFFFu, rB, o);
    }

    if (el == 0) {
        if (okA) out[eA] = rA;
        if (okB) out[eB] = rB;
    }
    if (lblout && el == 1) {
        if (okA) lblout[eA] = (float)lbl[eA];
        if (okB) lblout[eB] = (float)lbl[eB];
    }
}

extern "C" void kernel_launch(void* const* d_in, const int* in_sizes, int n_in,
                              void* d_out, int out_size)
{
    const float* x   = (const float*)d_in[0];
    const int*   ei  = (const int*)d_in[1];
    const int*   lbl = (const int*)d_in[2];
    const float* W1  = (const float*)d_in[3];
    const float* b1  = (const float*)d_in[4];
    const float* W2  = (const float*)d_in[5];
    const float* b2  = (const float*)d_in[6];

    int N = in_sizes[0] / DD;   // 100000
    int E = in_sizes[2];        // 500000

    uint4* h2h;
    cudaGetSymbolAddress((void**)&h2h, g_h2h);

    cudaFuncSetAttribute(mlp_fused_kernel,
                         cudaFuncAttributeMaxDynamicSharedMemorySize, SMEM_TOTAL);

    int T = (N + TILE - 1) / TILE;
    mlp_fused_kernel<<<NSM, 512, SMEM_TOTAL>>>(x, W1, W2, b1, b2, h2h, N, T);

    float* out = (float*)d_out;
    float* lblout = (out_size >= 2 * E) ? out + E : nullptr;
    int warps  = (E + 3) / 4;            // 4 edges per warp
    int blocks = (warps + 7) / 8;        // 8 warps per block
    edge_dot_kernel<<<blocks, 256>>>(h2h, ei, lbl, out, lblout, E, N);
}

// round 15
// speedup vs baseline: 1.0433x; 1.0383x over previous
#include <cuda_runtime.h>
#include <cuda_fp16.h>
#include <cstdint>

// ---------------------------------------------------------------------------
// GNNTransductiveEdgeHead, R15:
//  - MLP: persistent CTA, two 8-warp streams, 128-row tiles, fp16 GEMM
//    (fp32 accum), x/h1 split buffers (R14, frozen).
//  - edge dot: 16 lanes/edge, 8 edges/warp (8 independent LDG.128 per lane
//    for deeper MLP), half2-math dot.
// ---------------------------------------------------------------------------

#define DD 128
#define TILE 128           // rows per stream-tile
#define MAX_NODES 100000
#define NSM 148

// SMEM layout (bytes): rows are 128 fp16 = 256B, XOR-swizzled 16B chunks.
#define P_W1H 0
#define P_W2H 32768
#define A_BASE 65536       // stream g: XBUF = A_BASE + g*65536, H1BUF = +32768
#define B1_OFF 196608
#define B2_OFF 197120
#define SMEM_TOTAL 197632

__device__ uint4 g_h2h[MAX_NODES * 16];          // h2 as fp16, 256B per node

__device__ __forceinline__ uint32_t smem_u32(const void* p) {
    uint32_t a;
    asm("{ .reg .u64 t; cvta.to.shared.u64 t, %1; cvt.u32.u64 %0, t; }"
        : "=r"(a) : "l"(p));
    return a;
}
__device__ __forceinline__ void ldmatrix_x4(uint32_t& r0, uint32_t& r1,
                                            uint32_t& r2, uint32_t& r3,
                                            uint32_t addr) {
    asm volatile("ldmatrix.sync.aligned.m8n8.x4.shared.b16 {%0,%1,%2,%3}, [%4];"
                 : "=r"(r0), "=r"(r1), "=r"(r2), "=r"(r3) : "r"(addr));
}
__device__ __forceinline__ void ldmatrix_x4_trans(uint32_t& r0, uint32_t& r1,
                                                  uint32_t& r2, uint32_t& r3,
                                                  uint32_t addr) {
    asm volatile("ldmatrix.sync.aligned.m8n8.x4.trans.shared.b16 {%0,%1,%2,%3}, [%4];"
                 : "=r"(r0), "=r"(r1), "=r"(r2), "=r"(r3) : "r"(addr));
}
__device__ __forceinline__ void mma_f16(float* c, const uint32_t* a,
                                        uint32_t b0, uint32_t b1) {
    asm volatile(
        "mma.sync.aligned.m16n8k16.row.col.f32.f16.f16.f32 "
        "{%0,%1,%2,%3}, {%4,%5,%6,%7}, {%8,%9}, {%0,%1,%2,%3};"
        : "+f"(c[0]), "+f"(c[1]), "+f"(c[2]), "+f"(c[3])
        : "r"(a[0]), "r"(a[1]), "r"(a[2]), "r"(a[3]), "r"(b0), "r"(b1));
}
__device__ __forceinline__ uint32_t packh2(float x, float y) {
    __half2 h = __floats2half2_rn(x, y);
    return *(uint32_t*)&h;
}
#define GBAR(gid) asm volatile("bar.sync %0, %1;" :: "r"((gid) + 1), "r"(256) : "memory")

// fp16 MMA over one staged A tile vs one W panel: 8 ks x (6 LDSM + 16 HMMA).
__device__ __forceinline__ void mma_layer(float acc[4][4][4],
                                          uint32_t aB, uint32_t pB,
                                          int hA, int x7, int ng) {
#pragma unroll
    for (int ks = 0; ks < 8; ks++) {
        uint32_t ah[4][4];
#pragma unroll
        for (int mt = 0; mt < 4; mt++) {
            const uint32_t off = mt * 4096 + ((((2 * ks + hA) ^ x7)) << 4);
            ldmatrix_x4(ah[mt][0], ah[mt][1], ah[mt][2], ah[mt][3], aB + off);
        }
        uint32_t bh[4][2];
#pragma unroll
        for (int hf = 0; hf < 2; hf++) {
            const uint32_t off = ks * 4096 +
                ((((4 * ng + 2 * hf + hA) ^ x7)) << 4);
            uint32_t r0, r1, r2, r3;
            ldmatrix_x4_trans(r0, r1, r2, r3, pB + off);
            bh[2 * hf][0] = r0; bh[2 * hf][1] = r1;
            bh[2 * hf + 1][0] = r2; bh[2 * hf + 1][1] = r3;
        }
#pragma unroll
        for (int mt = 0; mt < 4; mt++)
#pragma unroll
            for (int nt = 0; nt < 4; nt++)
                mma_f16(acc[mt][nt], ah[mt], bh[nt][0], bh[nt][1]);
    }
}

// Stage one 128-row X tile (fp32 global -> fp16 swizzled smem buffer).
__device__ __forceinline__ void stage_tile(char* smem, uint32_t abuf,
                                           const float* __restrict__ X,
                                           int t, int N, int tg) {
    const int row = tg >> 1, hf = tg & 1;
    const int grow = t * TILE + row;
    const bool ok = grow < N;
    const float4* src = (const float4*)(X + (long long)grow * DD + hf * 64);
    char* d = smem + abuf + row * 256;
    const int r7 = row & 7;
#pragma unroll
    for (int q = 0; q < 8; q++) {
        float4 a = ok ? src[2 * q]     : make_float4(0, 0, 0, 0);
        float4 b = ok ? src[2 * q + 1] : make_float4(0, 0, 0, 0);
        uint4 v;
        v.x = packh2(a.x, a.y);
        v.y = packh2(a.z, a.w);
        v.z = packh2(b.x, b.y);
        v.w = packh2(b.z, b.w);
        *(uint4*)(d + (((8 * hf + q) ^ r7) << 4)) = v;
    }
}

// ---------------------------------------------------------------------------
// Persistent fused MLP (R14, frozen).
// ---------------------------------------------------------------------------
__global__ void __launch_bounds__(512, 1) mlp_fused_kernel(
    const float* __restrict__ X,
    const float* __restrict__ W1, const float* __restrict__ W2,
    const float* __restrict__ bias1, const float* __restrict__ bias2,
    uint4* __restrict__ H2h,
    int N, int T)
{
    extern __shared__ __align__(16) char smem[];
    const uint32_t sb = smem_u32(smem);
    const int tid  = threadIdx.x;
    const int g    = tid >> 8;        // stream 0/1
    const int tg   = tid & 255;
    const int warp = tg >> 5;
    const int lane = tid & 31;
    const int mg = warp & 1;
    const int ng = warp >> 1;

    // --- Prologue: load W fp32, convert to fp16, store swizzled ---
    {
        const float* wsrc[2] = {W1, W2};
        const uint32_t pdst[2] = {P_W1H, P_W2H};
#pragma unroll
        for (int i = 0; i < 8; i++) {
            int idx = tid + i * 512;          // 4096 chunks (16B fp16 each)
            int panel = idx >> 11;
            int rem   = idx & 2047;
            int row   = rem >> 4;
            int c     = rem & 15;             // chunk = 8 cols
            const float4* s = (const float4*)(wsrc[panel] + row * DD + c * 8);
            const float4 a = s[0], b = s[1];
            uint4 v;
            v.x = packh2(a.x, a.y);
            v.y = packh2(a.z, a.w);
            v.z = packh2(b.x, b.y);
            v.w = packh2(b.z, b.w);
            *(uint4*)(smem + pdst[panel] + row * 256 +
                      ((c ^ (row & 7)) << 4)) = v;
        }
    }
    if (tid < DD) {
        ((float*)(smem + B1_OFF))[tid] = bias1[tid];
        ((float*)(smem + B2_OFF))[tid] = bias2[tid];
    }

    const uint32_t XBUF  = A_BASE + g * 65536;
    const uint32_t H1BUF = XBUF + 32768;

    int t = 2 * blockIdx.x + g;
    if (t < T) stage_tile(smem, XBUF, X, t, N, tg);
    __syncthreads();   // W panels + first tiles visible

    const int hA = lane >> 4;
    const int x7 = lane & 7;
    const uint32_t aRow = (uint32_t)(mg * 64 + (lane & 15));
    const uint32_t aX  = sb + XBUF  + aRow * 256;
    const uint32_t aH1 = sb + H1BUF + aRow * 256;
    const uint32_t bRow = (uint32_t)(lane & 15) * 256;
    const uint32_t p1 = sb + P_W1H + bRow;
    const uint32_t p2 = sb + P_W2H + bRow;
    const float* sB1 = (const float*)(smem + B1_OFF);
    const float* sB2 = (const float*)(smem + B2_OFF);

    for (; t < T; t += 2 * NSM) {
        const int tn = t + 2 * NSM;
        const bool have_next = tn < T;

        float acc[4][4][4];
#pragma unroll
        for (int mt = 0; mt < 4; mt++)
#pragma unroll
            for (int nt = 0; nt < 4; nt++)
#pragma unroll
                for (int c = 0; c < 4; c++) acc[mt][nt][c] = 0.f;

        // ---- Layer 1 MMAs (read XBUF) ----
        mma_layer(acc, aX, p1, hA, x7, ng);
        GBAR(g);

        // ---- Epilogue 1: h1 = relu(acc+b1) -> H1BUF ----
#pragma unroll
        for (int mt = 0; mt < 4; mt++) {
            const int r0 = mg * 64 + mt * 16 + (lane >> 2);
            const int r1 = r0 + 8;
#pragma unroll
            for (int nt = 0; nt < 4; nt++) {
                const int cc = ng * 32 + nt * 8 + (lane & 3) * 2;
                const float bx = sB1[cc], by = sB1[cc + 1];
                const uint32_t w0 = ((4 * ng + nt) ^ (r0 & 7)) * 16 + 4 * (lane & 3);
                const uint32_t w1 = ((4 * ng + nt) ^ (r1 & 7)) * 16 + 4 * (lane & 3);
                *(uint32_t*)(smem + H1BUF + r0 * 256 + w0) =
                    packh2(fmaxf(acc[mt][nt][0] + bx, 0.f),
                           fmaxf(acc[mt][nt][1] + by, 0.f));
                *(uint32_t*)(smem + H1BUF + r1 * 256 + w1) =
                    packh2(fmaxf(acc[mt][nt][2] + bx, 0.f),
                           fmaxf(acc[mt][nt][3] + by, 0.f));
            }
        }

        // ---- Stage next tile into XBUF ----
        if (have_next) stage_tile(smem, XBUF, X, tn, N, tg);
        GBAR(g);   // h1 + next x visible

        // ---- Layer 2 MMAs (read H1BUF) ----
#pragma unroll
        for (int mt = 0; mt < 4; mt++)
#pragma unroll
            for (int nt = 0; nt < 4; nt++)
#pragma unroll
                for (int c = 0; c < 4; c++) acc[mt][nt][c] = 0.f;
        mma_layer(acc, aH1, p2, hA, x7, ng);

        // ---- Epilogue 2: h2 -> global fp16 (unfenced) ----
        {
            __half* H = (__half*)H2h;
            const int rowb = t * TILE + mg * 64;
#pragma unroll
            for (int mt = 0; mt < 4; mt++) {
                const int r0 = rowb + mt * 16 + (lane >> 2);
                const int r1 = r0 + 8;
                const bool ok0 = r0 < N, ok1 = r1 < N;
#pragma unroll
                for (int nt = 0; nt < 4; nt++) {
                    const int cc = ng * 32 + nt * 8 + (lane & 3) * 2;
                    const float bx = sB2[cc], by = sB2[cc + 1];
                    if (ok0) {
                        __half2 v = __floats2half2_rn(
                            fmaxf(acc[mt][nt][0] + bx, 0.f),
                            fmaxf(acc[mt][nt][1] + by, 0.f));
                        *(__half2*)(H + (long long)r0 * DD + cc) = v;
                    }
                    if (ok1) {
                        __half2 v = __floats2half2_rn(
                            fmaxf(acc[mt][nt][2] + bx, 0.f),
                            fmaxf(acc[mt][nt][3] + by, 0.f));
                        *(__half2*)(H + (long long)r1 * DD + cc) = v;
                    }
                }
            }
        }
    }
}

// ---------------------------------------------------------------------------
// Edge decode, R15: 16 lanes/edge, 8 edges/warp.
// Lane (eh=lane>>4, el=lane&15) handles edges base+eh+{0,2,4,6}; 8 LDG.128
// in flight per lane before any math.
// ---------------------------------------------------------------------------
__device__ __forceinline__ float dot16B(uint4 a, uint4 b) {
    __half2 p0 = __hmul2(*(const __half2*)&a.x, *(const __half2*)&b.x);
    p0 = __hfma2(*(const __half2*)&a.z, *(const __half2*)&b.z, p0);
    __half2 p1 = __hmul2(*(const __half2*)&a.y, *(const __half2*)&b.y);
    p1 = __hfma2(*(const __half2*)&a.w, *(const __half2*)&b.w, p1);
    const float2 f0 = __half22float2(p0);
    const float2 f1 = __half22float2(p1);
    return (f0.x + f0.y) + (f1.x + f1.y);
}

__global__ void __launch_bounds__(256) edge_dot_kernel(
    const uint4* __restrict__ H16,
    const int* __restrict__ edge_index,
    const int* __restrict__ lbl,
    float* __restrict__ out,
    float* __restrict__ lblout,
    int E, int N)
{
    const int gwarp = (blockIdx.x * blockDim.x + threadIdx.x) >> 5;
    const int lane  = threadIdx.x & 31;
    const int el = lane & 15;
    const int eh = lane >> 4;
    const int base = gwarp * 8;
    if (base >= E) return;

    int e[4];
    bool ok[4];
    int s[4], d[4];
#pragma unroll
    for (int k = 0; k < 4; k++) {
        e[k] = base + eh + 2 * k;
        ok[k] = e[k] < E;
        const int i = ok[k] ? e[k] : 0;
        int ss = edge_index[i];
        int dd = edge_index[E + i];
        s[k] = min(max(ss, 0), N - 1);
        d[k] = min(max(dd, 0), N - 1);
    }

    // 8 independent 16B gathers.
    uint4 vs[4], vd[4];
#pragma unroll
    for (int k = 0; k < 4; k++) {
        vs[k] = H16[s[k] * 16 + el];
        vd[k] = H16[d[k] * 16 + el];
    }

    float r[4];
#pragma unroll
    for (int k = 0; k < 4; k++) r[k] = dot16B(vs[k], vd[k]);

    // Reduce over the 16-lane group, 4 edges interleaved.
#pragma unroll
    for (int o = 8; o > 0; o >>= 1) {
#pragma unroll
        for (int k = 0; k < 4; k++)
            r[k] += __shfl_xor_sync(0xFFFFFFFFu, r[k], o);
    }

    if (el == 0) {
#pragma unroll
        for (int k = 0; k < 4; k++)
            if (ok[k]) out[e[k]] = r[k];
    }
    if (lblout && el == 1) {
#pragma unroll
        for (int k = 0; k < 4; k++)
            if (ok[k]) lblout[e[k]] = (float)lbl[e[k]];
    }
}

extern "C" void kernel_launch(void* const* d_in, const int* in_sizes, int n_in,
                              void* d_out, int out_size)
{
    const float* x   = (const float*)d_in[0];
    const int*   ei  = (const int*)d_in[1];
    const int*   lbl = (const int*)d_in[2];
    const float* W1  = (const float*)d_in[3];
    const float* b1  = (const float*)d_in[4];
    const float* W2  = (const float*)d_in[5];
    const float* b2  = (const float*)d_in[6];

    int N = in_sizes[0] / DD;   // 100000
    int E = in_sizes[2];        // 500000

    uint4* h2h;
    cudaGetSymbolAddress((void**)&h2h, g_h2h);

    cudaFuncSetAttribute(mlp_fused_kernel,
                         cudaFuncAttributeMaxDynamicSharedMemorySize, SMEM_TOTAL);

    int T = (N + TILE - 1) / TILE;
    mlp_fused_kernel<<<NSM, 512, SMEM_TOTAL>>>(x, W1, W2, b1, b2, h2h, N, T);

    float* out = (float*)d_out;
    float* lblout = (out_size >= 2 * E) ? out + E : nullptr;
    int warps  = (E + 7) / 8;            // 8 edges per warp
    int blocks = (warps + 7) / 8;        // 8 warps per block
    edge_dot_kernel<<<blocks, 256>>>(h2h, ei, lbl, out, lblout, E, N);
}